// round 6
// baseline (speedup 1.0000x reference)
#include <cuda_runtime.h>
#include <cstdint>
#include <math.h>

// ---------------------------------------------------------------------------
// GQA block: y = proj( attn( x@Wq^T, x@Wk^T, x@Wv^T ) )
//   x: (2, 2048, 1024) fp32;  Wq,Wproj: (1024,1024); Wk,Wv: (512,1024)
//   16 heads, 8 kv heads (GROUP=2), d_head=64, scale=1/8, non-causal softmax.
//
// Precision plan:
//   - Dense projections: SPLIT tf32 (hi/lo, 3 MMAs) -> ~fp32-accurate.
//   - Attention: single tf32 (errors enter softmax as tiny absolute shifts).
// Expected total rel_err ~3-5e-4 vs 1e-3 gate.
// ---------------------------------------------------------------------------

#define D_MODEL   1024
#define T_LEN     2048
#define BATCH     2
#define N_HEADS   16
#define D_HEAD    64
#define KV_DIM    512              // 8 kv heads * 64
#define ROWS      (BATCH * T_LEN)  // 4096
#define ATTN_SCALE 0.125f          // 64^-0.5

// Scratch (static device globals; no allocation APIs anywhere)
__device__ float g_Q[ROWS * D_MODEL];  // 16 MB
__device__ float g_K[ROWS * KV_DIM];   //  8 MB
__device__ float g_V[ROWS * KV_DIM];   //  8 MB
__device__ float g_Y[ROWS * D_MODEL];  // 16 MB

__device__ __forceinline__ uint32_t f2tf32(float x) {
    uint32_t y;
    asm("cvt.rna.tf32.f32 %0, %1;" : "=r"(y) : "f"(x));
    return y;
}

// hi = tf32(x); lo = tf32(x - hi)  (x - hi is exactly representable in fp32)
__device__ __forceinline__ uint2 split_tf32(float x) {
    uint2 r;
    r.x = f2tf32(x);
    r.y = f2tf32(x - __uint_as_float(r.x));
    return r;
}

__device__ __forceinline__ void mma_m16n8k8(float c[4], const uint32_t a[4],
                                            const uint32_t b[2]) {
    asm volatile(
        "mma.sync.aligned.m16n8k8.row.col.f32.tf32.tf32.f32 "
        "{%0,%1,%2,%3}, {%4,%5,%6,%7}, {%8,%9}, {%0,%1,%2,%3};"
        : "+f"(c[0]), "+f"(c[1]), "+f"(c[2]), "+f"(c[3])
        : "r"(a[0]), "r"(a[1]), "r"(a[2]), "r"(a[3]), "r"(b[0]), "r"(b[1]));
}

// ---------------------------------------------------------------------------
// Split-tf32 GEMM: C[M,N] = A[M,K] @ W[N,K]^T  (torch Linear convention)
// Block tile 128(M) x 64(N), 8 warps, each warp 16x64. k-step 16.
// Smem holds (hi,lo) tf32 pairs as uint2; row stride 20 uint2 (=40 words)
// -> fragment loads conflict-free per 16-lane 64-bit phase:
//    banks (40g + 2q) mod 32 = (8g + 2q) mod 32 distinct within each half-warp.
// Inner product: acc += Ah*Bh + Ah*Bl + Al*Bh  (drops Al*Bl ~ 2^-22).
// ---------------------------------------------------------------------------
__global__ __launch_bounds__(256) void gemm_tf32_split(
    const float* __restrict__ A, const float* __restrict__ W,
    float* __restrict__ C, int M, int N, int K) {
    __shared__ uint2 As[128 * 20];
    __shared__ uint2 Ws[64 * 20];

    const int tid  = threadIdx.x;
    const int warp = tid >> 5;
    const int lane = tid & 31;
    const int g    = lane >> 2;   // groupID 0..7
    const int q    = lane & 3;    // thread-in-group 0..3
    const int m0   = blockIdx.y * 128;
    const int n0   = blockIdx.x * 64;

    float acc[8][4];
#pragma unroll
    for (int nt = 0; nt < 8; nt++)
#pragma unroll
        for (int i = 0; i < 4; i++) acc[nt][i] = 0.f;

    for (int k0 = 0; k0 < K; k0 += 16) {
        // A tile: 128 x 16 = 512 float4, 2 per thread
#pragma unroll
        for (int i = 0; i < 2; i++) {
            int idx = tid + i * 256;
            int r = idx >> 2, c = (idx & 3) << 2;
            float4 v = *(const float4*)(A + (size_t)(m0 + r) * K + k0 + c);
            uint2* p = &As[r * 20 + c];
            p[0] = split_tf32(v.x); p[1] = split_tf32(v.y);
            p[2] = split_tf32(v.z); p[3] = split_tf32(v.w);
        }
        // W tile: 64 x 16 = 256 float4, 1 per thread
        {
            int r = tid >> 2, c = (tid & 3) << 2;
            float4 v = *(const float4*)(W + (size_t)(n0 + r) * K + k0 + c);
            uint2* p = &Ws[r * 20 + c];
            p[0] = split_tf32(v.x); p[1] = split_tf32(v.y);
            p[2] = split_tf32(v.z); p[3] = split_tf32(v.w);
        }
        __syncthreads();

        const int mr = warp * 16;
#pragma unroll
        for (int kk = 0; kk < 16; kk += 8) {
            uint2 a0 = As[(mr + g) * 20 + kk + q];
            uint2 a1 = As[(mr + g + 8) * 20 + kk + q];
            uint2 a2 = As[(mr + g) * 20 + kk + q + 4];
            uint2 a3 = As[(mr + g + 8) * 20 + kk + q + 4];
            uint32_t ah[4] = {a0.x, a1.x, a2.x, a3.x};
            uint32_t al[4] = {a0.y, a1.y, a2.y, a3.y};
#pragma unroll
            for (int nt = 0; nt < 8; nt++) {
                uint2 b0 = Ws[(nt * 8 + g) * 20 + kk + q];
                uint2 b1 = Ws[(nt * 8 + g) * 20 + kk + q + 4];
                uint32_t bh[2] = {b0.x, b1.x};
                uint32_t bl[2] = {b0.y, b1.y};
                mma_m16n8k8(acc[nt], ah, bh);
                mma_m16n8k8(acc[nt], ah, bl);
                mma_m16n8k8(acc[nt], al, bh);
            }
        }
        __syncthreads();
    }

    const int row = m0 + warp * 16 + g;
#pragma unroll
    for (int nt = 0; nt < 8; nt++) {
        int col = n0 + nt * 8 + q * 2;
        *(float2*)(C + (size_t)row * N + col) =
            make_float2(acc[nt][0], acc[nt][1]);
        *(float2*)(C + (size_t)(row + 8) * N + col) =
            make_float2(acc[nt][2], acc[nt][3]);
    }
}

// ---------------------------------------------------------------------------
// Flash attention (non-causal), single tf32. Grid (t/64, 16 heads, 2 batch),
// 128 threads. Each warp owns 16 q-rows x full 64-key tile -> softmax row
// reduce is 2x shfl.xor within each quad. K/V/P in smem tf32 bits, stride 68.
// ---------------------------------------------------------------------------
#define SMS 68
#define ATTN_SMEM (3 * 64 * SMS * 4)

__global__ __launch_bounds__(128) void attn_tf32(
    const float* __restrict__ Qg, const float* __restrict__ Kg,
    const float* __restrict__ Vg, float* __restrict__ Yg) {
    extern __shared__ uint32_t sm[];
    uint32_t* Ks = sm;                // [64][SMS]
    uint32_t* Vs = sm + 64 * SMS;     // [64][SMS]
    uint32_t* Ps = sm + 2 * 64 * SMS; // [64][SMS]

    const int tid  = threadIdx.x;
    const int warp = tid >> 5;
    const int lane = tid & 31;
    const int g    = lane >> 2;
    const int q    = lane & 3;
    const int b    = blockIdx.z;
    const int h    = blockIdx.y;
    const int qrow0 = blockIdx.x * 64 + warp * 16; // within-batch q row

    const float* Qp = Qg + (size_t)b * T_LEN * D_MODEL + h * D_HEAD;
    const float* Kp = Kg + (size_t)b * T_LEN * KV_DIM + (h >> 1) * D_HEAD;
    const float* Vp = Vg + (size_t)b * T_LEN * KV_DIM + (h >> 1) * D_HEAD;

    // Q fragments (this warp's 16 rows x d=64), converted once
    uint32_t qf[8][4];
#pragma unroll
    for (int kt = 0; kt < 8; kt++) {
        qf[kt][0] = f2tf32(Qp[(size_t)(qrow0 + g) * D_MODEL + kt * 8 + q]);
        qf[kt][1] = f2tf32(Qp[(size_t)(qrow0 + g + 8) * D_MODEL + kt * 8 + q]);
        qf[kt][2] = f2tf32(Qp[(size_t)(qrow0 + g) * D_MODEL + kt * 8 + q + 4]);
        qf[kt][3] = f2tf32(Qp[(size_t)(qrow0 + g + 8) * D_MODEL + kt * 8 + q + 4]);
    }

    float o[8][4];
#pragma unroll
    for (int nt = 0; nt < 8; nt++)
#pragma unroll
        for (int i = 0; i < 4; i++) o[nt][i] = 0.f;
    float mrow0 = -INFINITY, mrow1 = -INFINITY;
    float lrow0 = 0.f, lrow1 = 0.f;

    for (int s0 = 0; s0 < T_LEN; s0 += 64) {
        __syncthreads();  // previous tile fully consumed
        // Load K and V tiles (64 x 64 floats each); convert to tf32 in smem
#pragma unroll
        for (int i = 0; i < 8; i++) {
            int idx = tid + i * 128;
            int r = idx >> 4, c = (idx & 15) << 2;
            float4 kv = *(const float4*)(Kp + (size_t)(s0 + r) * KV_DIM + c);
            uint32_t* pk = &Ks[r * SMS + c];
            pk[0] = f2tf32(kv.x); pk[1] = f2tf32(kv.y);
            pk[2] = f2tf32(kv.z); pk[3] = f2tf32(kv.w);
            float4 vv = *(const float4*)(Vp + (size_t)(s0 + r) * KV_DIM + c);
            uint32_t* pv = &Vs[r * SMS + c];
            pv[0] = f2tf32(vv.x); pv[1] = f2tf32(vv.y);
            pv[2] = f2tf32(vv.z); pv[3] = f2tf32(vv.w);
        }
        __syncthreads();

        // S = Q @ K^T  (warp: 16 x 64)
        float sAcc[8][4];
#pragma unroll
        for (int nt = 0; nt < 8; nt++)
#pragma unroll
            for (int i = 0; i < 4; i++) sAcc[nt][i] = 0.f;
#pragma unroll
        for (int kt = 0; kt < 8; kt++) {
#pragma unroll
            for (int nt = 0; nt < 8; nt++) {
                uint32_t bfr[2];
                bfr[0] = Ks[(nt * 8 + g) * SMS + kt * 8 + q];
                bfr[1] = Ks[(nt * 8 + g) * SMS + kt * 8 + q + 4];
                mma_m16n8k8(sAcc[nt], qf[kt], bfr);
            }
        }

        // scale + row max
        float tmax0 = -INFINITY, tmax1 = -INFINITY;
#pragma unroll
        for (int nt = 0; nt < 8; nt++) {
            sAcc[nt][0] *= ATTN_SCALE; sAcc[nt][1] *= ATTN_SCALE;
            sAcc[nt][2] *= ATTN_SCALE; sAcc[nt][3] *= ATTN_SCALE;
            tmax0 = fmaxf(tmax0, fmaxf(sAcc[nt][0], sAcc[nt][1]));
            tmax1 = fmaxf(tmax1, fmaxf(sAcc[nt][2], sAcc[nt][3]));
        }
        tmax0 = fmaxf(tmax0, __shfl_xor_sync(0xffffffffu, tmax0, 1));
        tmax0 = fmaxf(tmax0, __shfl_xor_sync(0xffffffffu, tmax0, 2));
        tmax1 = fmaxf(tmax1, __shfl_xor_sync(0xffffffffu, tmax1, 1));
        tmax1 = fmaxf(tmax1, __shfl_xor_sync(0xffffffffu, tmax1, 2));

        float mn0 = fmaxf(mrow0, tmax0), mn1 = fmaxf(mrow1, tmax1);
        float corr0 = expf(mrow0 - mn0), corr1 = expf(mrow1 - mn1);

        // P = exp(S - m), written pre-converted to warp-private Ps rows
        float ps0 = 0.f, ps1 = 0.f;
        uint32_t* Pw0 = &Ps[(warp * 16 + g) * SMS];
        uint32_t* Pw1 = &Ps[(warp * 16 + g + 8) * SMS];
#pragma unroll
        for (int nt = 0; nt < 8; nt++) {
            float p00 = expf(sAcc[nt][0] - mn0);
            float p01 = expf(sAcc[nt][1] - mn0);
            float p10 = expf(sAcc[nt][2] - mn1);
            float p11 = expf(sAcc[nt][3] - mn1);
            ps0 += p00 + p01;
            ps1 += p10 + p11;
            Pw0[nt * 8 + 2 * q]     = f2tf32(p00);
            Pw0[nt * 8 + 2 * q + 1] = f2tf32(p01);
            Pw1[nt * 8 + 2 * q]     = f2tf32(p10);
            Pw1[nt * 8 + 2 * q + 1] = f2tf32(p11);
        }
        ps0 += __shfl_xor_sync(0xffffffffu, ps0, 1);
        ps0 += __shfl_xor_sync(0xffffffffu, ps0, 2);
        ps1 += __shfl_xor_sync(0xffffffffu, ps1, 1);
        ps1 += __shfl_xor_sync(0xffffffffu, ps1, 2);
        lrow0 = lrow0 * corr0 + ps0;
        lrow1 = lrow1 * corr1 + ps1;
        mrow0 = mn0; mrow1 = mn1;
#pragma unroll
        for (int nt = 0; nt < 8; nt++) {
            o[nt][0] *= corr0; o[nt][1] *= corr0;
            o[nt][2] *= corr1; o[nt][3] *= corr1;
        }
        __syncwarp();  // Ps visible (warp-private rows)

        // O += P @ V
#pragma unroll
        for (int kt = 0; kt < 8; kt++) {
            uint32_t a[4];
            a[0] = Ps[(warp * 16 + g) * SMS + kt * 8 + q];
            a[1] = Ps[(warp * 16 + g + 8) * SMS + kt * 8 + q];
            a[2] = Ps[(warp * 16 + g) * SMS + kt * 8 + q + 4];
            a[3] = Ps[(warp * 16 + g + 8) * SMS + kt * 8 + q + 4];
#pragma unroll
            for (int nt = 0; nt < 8; nt++) {
                uint32_t bfr[2];
                bfr[0] = Vs[(kt * 8 + q) * SMS + nt * 8 + g];
                bfr[1] = Vs[(kt * 8 + q + 4) * SMS + nt * 8 + g];
                mma_m16n8k8(o[nt], a, bfr);
            }
        }
    }

    // normalize + write Y (row-major (4096, 1024), head h at cols h*64..)
    float inv0 = 1.f / lrow0, inv1 = 1.f / lrow1;
    const size_t yb = (size_t)(b * T_LEN + qrow0 + g) * D_MODEL + h * D_HEAD;
#pragma unroll
    for (int nt = 0; nt < 8; nt++) {
        int col = nt * 8 + 2 * q;
        *(float2*)(Yg + yb + col) =
            make_float2(o[nt][0] * inv0, o[nt][1] * inv0);
        *(float2*)(Yg + yb + (size_t)8 * D_MODEL + col) =
            make_float2(o[nt][2] * inv1, o[nt][3] * inv1);
    }
}

// ---------------------------------------------------------------------------
extern "C" void kernel_launch(void* const* d_in, const int* in_sizes, int n_in,
                              void* d_out, int out_size) {
    (void)in_sizes; (void)n_in; (void)out_size;
    const float* x   = (const float*)d_in[0];
    const float* Wq  = (const float*)d_in[1];
    const float* Wk  = (const float*)d_in[2];
    const float* Wv  = (const float*)d_in[3];
    const float* Wpj = (const float*)d_in[4];
    float* out = (float*)d_out;

    float *pQ, *pK, *pV, *pY;
    cudaGetSymbolAddress((void**)&pQ, g_Q);
    cudaGetSymbolAddress((void**)&pK, g_K);
    cudaGetSymbolAddress((void**)&pV, g_V);
    cudaGetSymbolAddress((void**)&pY, g_Y);

    cudaFuncSetAttribute(attn_tf32,
                         cudaFuncAttributeMaxDynamicSharedMemorySize,
                         ATTN_SMEM);

    // Projections (split tf32, ~fp32 accurate)
    gemm_tf32_split<<<dim3(D_MODEL / 64, ROWS / 128), 256>>>(x, Wq, pQ, ROWS, D_MODEL, D_MODEL);
    gemm_tf32_split<<<dim3(KV_DIM / 64, ROWS / 128), 256>>>(x, Wk, pK, ROWS, KV_DIM, D_MODEL);
    gemm_tf32_split<<<dim3(KV_DIM / 64, ROWS / 128), 256>>>(x, Wv, pV, ROWS, KV_DIM, D_MODEL);
    // Attention (single tf32)
    attn_tf32<<<dim3(T_LEN / 64, N_HEADS, BATCH), 128, ATTN_SMEM>>>(pQ, pK, pV, pY);
    // Output projection (split tf32)
    gemm_tf32_split<<<dim3(D_MODEL / 64, ROWS / 128), 256>>>(pY, Wpj, out, ROWS, D_MODEL, D_MODEL);
}

// round 11
// speedup vs baseline: 1.0223x; 1.0223x over previous
#include <cuda_runtime.h>
#include <cstdint>
#include <math.h>

// ---------------------------------------------------------------------------
// GQA block: y = proj( attn( x@Wq^T, x@Wk^T, x@Wv^T ) )
// Split-tf32 projections (3 MMAs, ~fp32 accurate), single-tf32 flash attn.
// R6 changes: 32-row warp tiles everywhere (halve B-fragment LDS per MMA),
// GEMM register prefetch (hide LDG), ex2.approx softmax with folded scale.
// ---------------------------------------------------------------------------

#define D_MODEL   1024
#define T_LEN     2048
#define BATCH     2
#define N_HEADS   16
#define D_HEAD    64
#define KV_DIM    512
#define ROWS      (BATCH * T_LEN)  // 4096
// scale * log2(e) folded into Q fragments
#define QSC 0.18033688011112042f

__device__ float g_Q[ROWS * D_MODEL];
__device__ float g_K[ROWS * KV_DIM];
__device__ float g_V[ROWS * KV_DIM];
__device__ float g_Y[ROWS * D_MODEL];

__device__ __forceinline__ uint32_t f2tf32(float x) {
    uint32_t y;
    asm("cvt.rna.tf32.f32 %0, %1;" : "=r"(y) : "f"(x));
    return y;
}
__device__ __forceinline__ uint2 split_tf32(float x) {
    uint2 r;
    r.x = f2tf32(x);
    r.y = f2tf32(x - __uint_as_float(r.x));
    return r;
}
__device__ __forceinline__ float fex2(float x) {
    float y;
    asm("ex2.approx.f32 %0, %1;" : "=f"(y) : "f"(x));
    return y;
}
__device__ __forceinline__ void mma_m16n8k8(float c[4], const uint32_t a[4],
                                            const uint32_t b[2]) {
    asm volatile(
        "mma.sync.aligned.m16n8k8.row.col.f32.tf32.tf32.f32 "
        "{%0,%1,%2,%3}, {%4,%5,%6,%7}, {%8,%9}, {%0,%1,%2,%3};"
        : "+f"(c[0]), "+f"(c[1]), "+f"(c[2]), "+f"(c[3])
        : "r"(a[0]), "r"(a[1]), "r"(a[2]), "r"(a[3]), "r"(b[0]), "r"(b[1]));
}

// ---------------------------------------------------------------------------
// Split-tf32 GEMM: C[M,N] = A[M,K] @ W[N,K]^T. Block 128x64, 4 warps,
// warp tile 32x64, k-step 16, register prefetch of the next k-tile.
// Smem (hi,lo) uint2 rows, stride 20 -> conflict-free 64b fragment phases.
// ---------------------------------------------------------------------------
__global__ __launch_bounds__(128) void gemm_tf32_split(
    const float* __restrict__ A, const float* __restrict__ W,
    float* __restrict__ C, int M, int N, int K) {
    __shared__ uint2 As[128 * 20];
    __shared__ uint2 Ws[64 * 20];

    const int tid  = threadIdx.x;
    const int warp = tid >> 5;
    const int lane = tid & 31;
    const int g    = lane >> 2;
    const int q    = lane & 3;
    const int m0   = blockIdx.y * 128;
    const int n0   = blockIdx.x * 64;

    float4 pa[4], pw[2];
    // preload k-tile 0
#pragma unroll
    for (int i = 0; i < 4; i++) {
        int idx = tid + i * 128, r = idx >> 2, c = (idx & 3) << 2;
        pa[i] = *(const float4*)(A + (size_t)(m0 + r) * K + c);
    }
#pragma unroll
    for (int i = 0; i < 2; i++) {
        int idx = tid + i * 128, r = idx >> 2, c = (idx & 3) << 2;
        pw[i] = *(const float4*)(W + (size_t)(n0 + r) * K + c);
    }

    float acc[2][8][4];
#pragma unroll
    for (int m = 0; m < 2; m++)
#pragma unroll
        for (int nt = 0; nt < 8; nt++)
#pragma unroll
            for (int i = 0; i < 4; i++) acc[m][nt][i] = 0.f;

    for (int k0 = 0; k0 < K; k0 += 16) {
        // store prefetched tile (convert once at store time)
#pragma unroll
        for (int i = 0; i < 4; i++) {
            int idx = tid + i * 128, r = idx >> 2, c = (idx & 3) << 2;
            uint2* p = &As[r * 20 + c];
            p[0] = split_tf32(pa[i].x); p[1] = split_tf32(pa[i].y);
            p[2] = split_tf32(pa[i].z); p[3] = split_tf32(pa[i].w);
        }
#pragma unroll
        for (int i = 0; i < 2; i++) {
            int idx = tid + i * 128, r = idx >> 2, c = (idx & 3) << 2;
            uint2* p = &Ws[r * 20 + c];
            p[0] = split_tf32(pw[i].x); p[1] = split_tf32(pw[i].y);
            p[2] = split_tf32(pw[i].z); p[3] = split_tf32(pw[i].w);
        }
        __syncthreads();

        // issue next tile's LDG early; latency hidden behind the MMA loop
        if (k0 + 16 < K) {
            const int kn = k0 + 16;
#pragma unroll
            for (int i = 0; i < 4; i++) {
                int idx = tid + i * 128, r = idx >> 2, c = (idx & 3) << 2;
                pa[i] = *(const float4*)(A + (size_t)(m0 + r) * K + kn + c);
            }
#pragma unroll
            for (int i = 0; i < 2; i++) {
                int idx = tid + i * 128, r = idx >> 2, c = (idx & 3) << 2;
                pw[i] = *(const float4*)(W + (size_t)(n0 + r) * K + kn + c);
            }
        }

        const int mr = warp * 32;
#pragma unroll
        for (int kk = 0; kk < 16; kk += 8) {
            uint32_t ah[2][4], al[2][4];
#pragma unroll
            for (int m = 0; m < 2; m++) {
                uint2 a0 = As[(mr + m * 16 + g) * 20 + kk + q];
                uint2 a1 = As[(mr + m * 16 + g + 8) * 20 + kk + q];
                uint2 a2 = As[(mr + m * 16 + g) * 20 + kk + q + 4];
                uint2 a3 = As[(mr + m * 16 + g + 8) * 20 + kk + q + 4];
                ah[m][0] = a0.x; ah[m][1] = a1.x; ah[m][2] = a2.x; ah[m][3] = a3.x;
                al[m][0] = a0.y; al[m][1] = a1.y; al[m][2] = a2.y; al[m][3] = a3.y;
            }
#pragma unroll
            for (int nt = 0; nt < 8; nt++) {
                uint2 b0 = Ws[(nt * 8 + g) * 20 + kk + q];
                uint2 b1 = Ws[(nt * 8 + g) * 20 + kk + q + 4];
                uint32_t bh[2] = {b0.x, b1.x};
                uint32_t bl[2] = {b0.y, b1.y};
#pragma unroll
                for (int m = 0; m < 2; m++) {
                    mma_m16n8k8(acc[m][nt], ah[m], bh);
                    mma_m16n8k8(acc[m][nt], ah[m], bl);
                    mma_m16n8k8(acc[m][nt], al[m], bh);
                }
            }
        }
        __syncthreads();
    }

#pragma unroll
    for (int m = 0; m < 2; m++) {
        const int row = m0 + warp * 32 + m * 16 + g;
#pragma unroll
        for (int nt = 0; nt < 8; nt++) {
            int col = n0 + nt * 8 + q * 2;
            *(float2*)(C + (size_t)row * N + col) =
                make_float2(acc[m][nt][0], acc[m][nt][1]);
            *(float2*)(C + (size_t)(row + 8) * N + col) =
                make_float2(acc[m][nt][2], acc[m][nt][3]);
        }
    }
}

// ---------------------------------------------------------------------------
// Flash attention (non-causal), single tf32. Block = 128 q-rows (4 warps x 32
// rows), key tile 32. Each K/V B-fragment feeds TWO m16 MMAs -> half the LDS
// per MMA of the 16-row version. ex2.approx softmax, scale folded into Q.
// Smem 35.8 KB (static).
// ---------------------------------------------------------------------------
#define SMS 68   // K/V row stride (words): banks (4g+q) distinct
#define PSS 36   // P row stride (words)

__global__ __launch_bounds__(128) void attn_tf32(
    const float* __restrict__ Qg, const float* __restrict__ Kg,
    const float* __restrict__ Vg, float* __restrict__ Yg) {
    __shared__ uint32_t Ks[32 * SMS];
    __shared__ uint32_t Vs[32 * SMS];
    __shared__ uint32_t Ps[128 * PSS];

    const int tid  = threadIdx.x;
    const int warp = tid >> 5;
    const int lane = tid & 31;
    const int g    = lane >> 2;
    const int q    = lane & 3;
    const int b    = blockIdx.z;
    const int h    = blockIdx.y;
    const int qrow0 = blockIdx.x * 128 + warp * 32;

    const float* Qp = Qg + (size_t)b * T_LEN * D_MODEL + h * D_HEAD;
    const float* Kp = Kg + (size_t)b * T_LEN * KV_DIM + (h >> 1) * D_HEAD;
    const float* Vp = Vg + (size_t)b * T_LEN * KV_DIM + (h >> 1) * D_HEAD;

    // Q fragments: 2 m-blocks x 8 k-frags, pre-scaled by scale*log2e
    uint32_t qf[2][8][4];
#pragma unroll
    for (int m = 0; m < 2; m++) {
        const float* Q0 = Qp + (size_t)(qrow0 + m * 16 + g) * D_MODEL;
        const float* Q1 = Qp + (size_t)(qrow0 + m * 16 + g + 8) * D_MODEL;
#pragma unroll
        for (int kt = 0; kt < 8; kt++) {
            qf[m][kt][0] = f2tf32(Q0[kt * 8 + q] * QSC);
            qf[m][kt][1] = f2tf32(Q1[kt * 8 + q] * QSC);
            qf[m][kt][2] = f2tf32(Q0[kt * 8 + q + 4] * QSC);
            qf[m][kt][3] = f2tf32(Q1[kt * 8 + q + 4] * QSC);
        }
    }

    float o[2][8][4];
#pragma unroll
    for (int m = 0; m < 2; m++)
#pragma unroll
        for (int nt = 0; nt < 8; nt++)
#pragma unroll
            for (int i = 0; i < 4; i++) o[m][nt][i] = 0.f;
    float mx[2][2] = {{-INFINITY, -INFINITY}, {-INFINITY, -INFINITY}};
    float lx[2][2] = {{0.f, 0.f}, {0.f, 0.f}};

    for (int s0 = 0; s0 < T_LEN; s0 += 32) {
        __syncthreads();
        // fill K/V tiles (32 x 64 each), tf32-converted at store
#pragma unroll
        for (int i = 0; i < 4; i++) {
            int idx = tid + i * 128;
            int r = idx >> 4, c = (idx & 15) << 2;
            float4 kv = *(const float4*)(Kp + (size_t)(s0 + r) * KV_DIM + c);
            uint32_t* pk = &Ks[r * SMS + c];
            pk[0] = f2tf32(kv.x); pk[1] = f2tf32(kv.y);
            pk[2] = f2tf32(kv.z); pk[3] = f2tf32(kv.w);
            float4 vv = *(const float4*)(Vp + (size_t)(s0 + r) * KV_DIM + c);
            uint32_t* pv = &Vs[r * SMS + c];
            pv[0] = f2tf32(vv.x); pv[1] = f2tf32(vv.y);
            pv[2] = f2tf32(vv.z); pv[3] = f2tf32(vv.w);
        }
        __syncthreads();

        // S = Q @ K^T : 2 m-blocks share every K B-fragment
        float sA[2][4][4];
#pragma unroll
        for (int m = 0; m < 2; m++)
#pragma unroll
            for (int nt = 0; nt < 4; nt++)
#pragma unroll
                for (int i = 0; i < 4; i++) sA[m][nt][i] = 0.f;
#pragma unroll
        for (int kt = 0; kt < 8; kt++) {
#pragma unroll
            for (int nt = 0; nt < 4; nt++) {
                uint32_t bfr[2];
                bfr[0] = Ks[(nt * 8 + g) * SMS + kt * 8 + q];
                bfr[1] = Ks[(nt * 8 + g) * SMS + kt * 8 + q + 4];
                mma_m16n8k8(sA[0][nt], qf[0][kt], bfr);
                mma_m16n8k8(sA[1][nt], qf[1][kt], bfr);
            }
        }

        // online softmax per m-block (values already in log2 domain)
#pragma unroll
        for (int m = 0; m < 2; m++) {
            float t0 = -INFINITY, t1 = -INFINITY;
#pragma unroll
            for (int nt = 0; nt < 4; nt++) {
                t0 = fmaxf(t0, fmaxf(sA[m][nt][0], sA[m][nt][1]));
                t1 = fmaxf(t1, fmaxf(sA[m][nt][2], sA[m][nt][3]));
            }
            t0 = fmaxf(t0, __shfl_xor_sync(0xffffffffu, t0, 1));
            t0 = fmaxf(t0, __shfl_xor_sync(0xffffffffu, t0, 2));
            t1 = fmaxf(t1, __shfl_xor_sync(0xffffffffu, t1, 1));
            t1 = fmaxf(t1, __shfl_xor_sync(0xffffffffu, t1, 2));
            float nm0 = fmaxf(mx[m][0], t0), nm1 = fmaxf(mx[m][1], t1);
            float c0 = fex2(mx[m][0] - nm0), c1 = fex2(mx[m][1] - nm1);

            uint32_t* P0 = &Ps[(warp * 32 + m * 16 + g) * PSS];
            uint32_t* P1 = &Ps[(warp * 32 + m * 16 + g + 8) * PSS];
            float ps0 = 0.f, ps1 = 0.f;
#pragma unroll
            for (int nt = 0; nt < 4; nt++) {
                float p00 = fex2(sA[m][nt][0] - nm0);
                float p01 = fex2(sA[m][nt][1] - nm0);
                float p10 = fex2(sA[m][nt][2] - nm1);
                float p11 = fex2(sA[m][nt][3] - nm1);
                ps0 += p00 + p01;
                ps1 += p10 + p11;
                P0[nt * 8 + 2 * q]     = f2tf32(p00);
                P0[nt * 8 + 2 * q + 1] = f2tf32(p01);
                P1[nt * 8 + 2 * q]     = f2tf32(p10);
                P1[nt * 8 + 2 * q + 1] = f2tf32(p11);
            }
            ps0 += __shfl_xor_sync(0xffffffffu, ps0, 1);
            ps0 += __shfl_xor_sync(0xffffffffu, ps0, 2);
            ps1 += __shfl_xor_sync(0xffffffffu, ps1, 1);
            ps1 += __shfl_xor_sync(0xffffffffu, ps1, 2);
            lx[m][0] = lx[m][0] * c0 + ps0;
            lx[m][1] = lx[m][1] * c1 + ps1;
            mx[m][0] = nm0; mx[m][1] = nm1;
#pragma unroll
            for (int nt = 0; nt < 8; nt++) {
                o[m][nt][0] *= c0; o[m][nt][1] *= c0;
                o[m][nt][2] *= c1; o[m][nt][3] *= c1;
            }
        }
        __syncwarp();  // Ps rows are warp-private

        // O += P @ V : both m-blocks share every V B-fragment
#pragma unroll
        for (int kt = 0; kt < 4; kt++) {
            uint32_t a0[4], a1[4];
            a0[0] = Ps[(warp * 32 + g) * PSS + kt * 8 + q];
            a0[1] = Ps[(warp * 32 + g + 8) * PSS + kt * 8 + q];
            a0[2] = Ps[(warp * 32 + g) * PSS + kt * 8 + q + 4];
            a0[3] = Ps[(warp * 32 + g + 8) * PSS + kt * 8 + q + 4];
            a1[0] = Ps[(warp * 32 + 16 + g) * PSS + kt * 8 + q];
            a1[1] = Ps[(warp * 32 + 16 + g + 8) * PSS + kt * 8 + q];
            a1[2] = Ps[(warp * 32 + 16 + g) * PSS + kt * 8 + q + 4];
            a1[3] = Ps[(warp * 32 + 16 + g + 8) * PSS + kt * 8 + q + 4];
#pragma unroll
            for (int nt = 0; nt < 8; nt++) {
                uint32_t bfr[2];
                bfr[0] = Vs[(kt * 8 + q) * SMS + nt * 8 + g];
                bfr[1] = Vs[(kt * 8 + q + 4) * SMS + nt * 8 + g];
                mma_m16n8k8(o[0][nt], a0, bfr);
                mma_m16n8k8(o[1][nt], a1, bfr);
            }
        }
    }

    // normalize + write Y
#pragma unroll
    for (int m = 0; m < 2; m++) {
        float inv0 = 1.f / lx[m][0], inv1 = 1.f / lx[m][1];
        const size_t yb =
            (size_t)(b * T_LEN + qrow0 + m * 16 + g) * D_MODEL + h * D_HEAD;
#pragma unroll
        for (int nt = 0; nt < 8; nt++) {
            int col = nt * 8 + 2 * q;
            *(float2*)(Yg + yb + col) =
                make_float2(o[m][nt][0] * inv0, o[m][nt][1] * inv0);
            *(float2*)(Yg + yb + (size_t)8 * D_MODEL + col) =
                make_float2(o[m][nt][2] * inv1, o[m][nt][3] * inv1);
        }
    }
}

// ---------------------------------------------------------------------------
extern "C" void kernel_launch(void* const* d_in, const int* in_sizes, int n_in,
                              void* d_out, int out_size) {
    (void)in_sizes; (void)n_in; (void)out_size;
    const float* x   = (const float*)d_in[0];
    const float* Wq  = (const float*)d_in[1];
    const float* Wk  = (const float*)d_in[2];
    const float* Wv  = (const float*)d_in[3];
    const float* Wpj = (const float*)d_in[4];
    float* out = (float*)d_out;

    float *pQ, *pK, *pV, *pY;
    cudaGetSymbolAddress((void**)&pQ, g_Q);
    cudaGetSymbolAddress((void**)&pK, g_K);
    cudaGetSymbolAddress((void**)&pV, g_V);
    cudaGetSymbolAddress((void**)&pY, g_Y);

    gemm_tf32_split<<<dim3(D_MODEL / 64, ROWS / 128), 128>>>(x, Wq, pQ, ROWS, D_MODEL, D_MODEL);
    gemm_tf32_split<<<dim3(KV_DIM / 64, ROWS / 128), 128>>>(x, Wk, pK, ROWS, KV_DIM, D_MODEL);
    gemm_tf32_split<<<dim3(KV_DIM / 64, ROWS / 128), 128>>>(x, Wv, pV, ROWS, KV_DIM, D_MODEL);
    attn_tf32<<<dim3(T_LEN / 128, N_HEADS, BATCH), 128>>>(pQ, pK, pV, pY);
    gemm_tf32_split<<<dim3(D_MODEL / 64, ROWS / 128), 128>>>(pY, Wpj, out, ROWS, D_MODEL, D_MODEL);
}

// round 12
// speedup vs baseline: 1.5066x; 1.4737x over previous
#include <cuda_runtime.h>
#include <cuda_bf16.h>
#include <cstdint>
#include <math.h>

// ---------------------------------------------------------------------------
// GQA block: y = proj( attn( x@Wq^T, x@Wk^T, x@Wv^T ) )
// R11: projections use SPLIT-BF16 (hi/lo, 3 x m16n8k16 per K=16) -> half the
// MMA count and half the LDS of split-tf32 at ~16-bit effective mantissa.
// QKV fused into one launch. Attention unchanged (tf32 flash, 305us).
// ---------------------------------------------------------------------------

#define D_MODEL   1024
#define T_LEN     2048
#define BATCH     2
#define N_HEADS   16
#define D_HEAD    64
#define KV_DIM    512
#define ROWS      (BATCH * T_LEN)  // 4096
#define QSC 0.18033688011112042f   // scale * log2(e)

__device__ float g_Q[ROWS * D_MODEL];
__device__ float g_K[ROWS * KV_DIM];
__device__ float g_V[ROWS * KV_DIM];
__device__ float g_Y[ROWS * D_MODEL];

__device__ __forceinline__ uint32_t f2tf32(float x) {
    uint32_t y;
    asm("cvt.rna.tf32.f32 %0, %1;" : "=r"(y) : "f"(x));
    return y;
}
__device__ __forceinline__ float fex2(float x) {
    float y;
    asm("ex2.approx.f32 %0, %1;" : "=f"(y) : "f"(x));
    return y;
}
// Pack two consecutive floats into (hi bf16 pair, lo bf16 pair)
__device__ __forceinline__ uint2 split2_bf16(float x, float y) {
    __nv_bfloat16 hx = __float2bfloat16_rn(x);
    __nv_bfloat16 hy = __float2bfloat16_rn(y);
    __nv_bfloat16 lx = __float2bfloat16_rn(x - __bfloat162float(hx));
    __nv_bfloat16 ly = __float2bfloat16_rn(y - __bfloat162float(hy));
    uint2 r;
    r.x = ((uint32_t)__bfloat16_as_ushort(hy) << 16) | __bfloat16_as_ushort(hx);
    r.y = ((uint32_t)__bfloat16_as_ushort(ly) << 16) | __bfloat16_as_ushort(lx);
    return r;
}
__device__ __forceinline__ void mma_bf16_k16(float c[4], const uint32_t a[4],
                                             const uint32_t b[2]) {
    asm volatile(
        "mma.sync.aligned.m16n8k16.row.col.f32.bf16.bf16.f32 "
        "{%0,%1,%2,%3}, {%4,%5,%6,%7}, {%8,%9}, {%0,%1,%2,%3};"
        : "+f"(c[0]), "+f"(c[1]), "+f"(c[2]), "+f"(c[3])
        : "r"(a[0]), "r"(a[1]), "r"(a[2]), "r"(a[3]), "r"(b[0]), "r"(b[1]));
}
__device__ __forceinline__ void mma_m16n8k8(float c[4], const uint32_t a[4],
                                            const uint32_t b[2]) {
    asm volatile(
        "mma.sync.aligned.m16n8k8.row.col.f32.tf32.tf32.f32 "
        "{%0,%1,%2,%3}, {%4,%5,%6,%7}, {%8,%9}, {%0,%1,%2,%3};"
        : "+f"(c[0]), "+f"(c[1]), "+f"(c[2]), "+f"(c[3])
        : "r"(a[0]), "r"(a[1]), "r"(a[2]), "r"(a[3]), "r"(b[0]), "r"(b[1]));
}

// ---------------------------------------------------------------------------
// Split-bf16 GEMM body: C[M,N] = A[M,K] @ W[N,K]^T.
// Block 128x64, 4 warps, warp tile 32x64, k-step 16, register prefetch.
// Smem rows: 8 used uint2 (kpairs) + 4 pad = stride 12 uint2 (24 words);
// all 64-bit fragment phases bank-conflict-free (24g+2q distinct mod 32).
// Inner: acc += Ah*Bh + Ah*Bl + Al*Bh   (Al*Bl ~ 2^-16, dropped)
// ---------------------------------------------------------------------------
__device__ __forceinline__ void gemm_body(
    const float* __restrict__ A, const float* __restrict__ W,
    float* __restrict__ C, int m0, int n0, int N, int K,
    uint2* As, uint2* Ws) {
    const int tid  = threadIdx.x;
    const int warp = tid >> 5;
    const int lane = tid & 31;
    const int g    = lane >> 2;
    const int q    = lane & 3;

    float4 pa[4], pw[2];
#pragma unroll
    for (int i = 0; i < 4; i++) {
        int idx = tid + i * 128, r = idx >> 2, c = (idx & 3) << 2;
        pa[i] = *(const float4*)(A + (size_t)(m0 + r) * K + c);
    }
#pragma unroll
    for (int i = 0; i < 2; i++) {
        int idx = tid + i * 128, r = idx >> 2, c = (idx & 3) << 2;
        pw[i] = *(const float4*)(W + (size_t)(n0 + r) * K + c);
    }

    float acc[2][8][4];
#pragma unroll
    for (int m = 0; m < 2; m++)
#pragma unroll
        for (int nt = 0; nt < 8; nt++)
#pragma unroll
            for (int i = 0; i < 4; i++) acc[m][nt][i] = 0.f;

    for (int k0 = 0; k0 < K; k0 += 16) {
#pragma unroll
        for (int i = 0; i < 4; i++) {
            int idx = tid + i * 128, r = idx >> 2, kp = (idx & 3) << 1;
            As[r * 12 + kp]     = split2_bf16(pa[i].x, pa[i].y);
            As[r * 12 + kp + 1] = split2_bf16(pa[i].z, pa[i].w);
        }
#pragma unroll
        for (int i = 0; i < 2; i++) {
            int idx = tid + i * 128, r = idx >> 2, kp = (idx & 3) << 1;
            Ws[r * 12 + kp]     = split2_bf16(pw[i].x, pw[i].y);
            Ws[r * 12 + kp + 1] = split2_bf16(pw[i].z, pw[i].w);
        }
        __syncthreads();

        if (k0 + 16 < K) {
            const int kn = k0 + 16;
#pragma unroll
            for (int i = 0; i < 4; i++) {
                int idx = tid + i * 128, r = idx >> 2, c = (idx & 3) << 2;
                pa[i] = *(const float4*)(A + (size_t)(m0 + r) * K + kn + c);
            }
#pragma unroll
            for (int i = 0; i < 2; i++) {
                int idx = tid + i * 128, r = idx >> 2, c = (idx & 3) << 2;
                pw[i] = *(const float4*)(W + (size_t)(n0 + r) * K + kn + c);
            }
        }

        const int mr = warp * 32;
        uint32_t ah[2][4], al[2][4];
#pragma unroll
        for (int m = 0; m < 2; m++) {
            uint2 a0 = As[(mr + m * 16 + g) * 12 + q];
            uint2 a1 = As[(mr + m * 16 + g + 8) * 12 + q];
            uint2 a2 = As[(mr + m * 16 + g) * 12 + q + 4];
            uint2 a3 = As[(mr + m * 16 + g + 8) * 12 + q + 4];
            ah[m][0] = a0.x; ah[m][1] = a1.x; ah[m][2] = a2.x; ah[m][3] = a3.x;
            al[m][0] = a0.y; al[m][1] = a1.y; al[m][2] = a2.y; al[m][3] = a3.y;
        }
#pragma unroll
        for (int nt = 0; nt < 8; nt++) {
            uint2 b0 = Ws[(nt * 8 + g) * 12 + q];
            uint2 b1 = Ws[(nt * 8 + g) * 12 + q + 4];
            uint32_t bh[2] = {b0.x, b1.x};
            uint32_t bl[2] = {b0.y, b1.y};
#pragma unroll
            for (int m = 0; m < 2; m++) {
                mma_bf16_k16(acc[m][nt], ah[m], bh);
                mma_bf16_k16(acc[m][nt], ah[m], bl);
                mma_bf16_k16(acc[m][nt], al[m], bh);
            }
        }
        __syncthreads();
    }

#pragma unroll
    for (int m = 0; m < 2; m++) {
        const int warp_ = threadIdx.x >> 5;
        const int row = m0 + warp_ * 32 + m * 16 + g;
#pragma unroll
        for (int nt = 0; nt < 8; nt++) {
            int col = n0 + nt * 8 + q * 2;
            *(float2*)(C + (size_t)row * N + col) =
                make_float2(acc[m][nt][0], acc[m][nt][1]);
            *(float2*)(C + (size_t)(row + 8) * N + col) =
                make_float2(acc[m][nt][2], acc[m][nt][3]);
        }
    }
}

// Fused QKV projection: gridDim.x covers concatenated N = 1024|512|512.
__global__ __launch_bounds__(128) void gemm_qkv(
    const float* __restrict__ x,
    const float* __restrict__ Wq, const float* __restrict__ Wk,
    const float* __restrict__ Wv,
    float* __restrict__ Q, float* __restrict__ K, float* __restrict__ V) {
    __shared__ uint2 As[128 * 12];
    __shared__ uint2 Ws[64 * 12];
    const int n0g = blockIdx.x * 64;
    const int m0  = blockIdx.y * 128;
    const float* W; float* C; int n0, N;
    if (n0g < 1024)      { W = Wq; C = Q; n0 = n0g;        N = 1024; }
    else if (n0g < 1536) { W = Wk; C = K; n0 = n0g - 1024; N = 512;  }
    else                 { W = Wv; C = V; n0 = n0g - 1536; N = 512;  }
    gemm_body(x, W, C, m0, n0, N, D_MODEL, As, Ws);
}

__global__ __launch_bounds__(128) void gemm_proj(
    const float* __restrict__ A, const float* __restrict__ W,
    float* __restrict__ C) {
    __shared__ uint2 As[128 * 12];
    __shared__ uint2 Ws[64 * 12];
    gemm_body(A, W, C, blockIdx.y * 128, blockIdx.x * 64, D_MODEL, D_MODEL,
              As, Ws);
}

// ---------------------------------------------------------------------------
// Flash attention (non-causal), single tf32 — unchanged from R6.
// ---------------------------------------------------------------------------
#define SMS 68
#define PSS 36

__global__ __launch_bounds__(128) void attn_tf32(
    const float* __restrict__ Qg, const float* __restrict__ Kg,
    const float* __restrict__ Vg, float* __restrict__ Yg) {
    __shared__ uint32_t Ks[32 * SMS];
    __shared__ uint32_t Vs[32 * SMS];
    __shared__ uint32_t Ps[128 * PSS];

    const int tid  = threadIdx.x;
    const int warp = tid >> 5;
    const int lane = tid & 31;
    const int g    = lane >> 2;
    const int q    = lane & 3;
    const int b    = blockIdx.z;
    const int h    = blockIdx.y;
    const int qrow0 = blockIdx.x * 128 + warp * 32;

    const float* Qp = Qg + (size_t)b * T_LEN * D_MODEL + h * D_HEAD;
    const float* Kp = Kg + (size_t)b * T_LEN * KV_DIM + (h >> 1) * D_HEAD;
    const float* Vp = Vg + (size_t)b * T_LEN * KV_DIM + (h >> 1) * D_HEAD;

    uint32_t qf[2][8][4];
#pragma unroll
    for (int m = 0; m < 2; m++) {
        const float* Q0 = Qp + (size_t)(qrow0 + m * 16 + g) * D_MODEL;
        const float* Q1 = Qp + (size_t)(qrow0 + m * 16 + g + 8) * D_MODEL;
#pragma unroll
        for (int kt = 0; kt < 8; kt++) {
            qf[m][kt][0] = f2tf32(Q0[kt * 8 + q] * QSC);
            qf[m][kt][1] = f2tf32(Q1[kt * 8 + q] * QSC);
            qf[m][kt][2] = f2tf32(Q0[kt * 8 + q + 4] * QSC);
            qf[m][kt][3] = f2tf32(Q1[kt * 8 + q + 4] * QSC);
        }
    }

    float o[2][8][4];
#pragma unroll
    for (int m = 0; m < 2; m++)
#pragma unroll
        for (int nt = 0; nt < 8; nt++)
#pragma unroll
            for (int i = 0; i < 4; i++) o[m][nt][i] = 0.f;
    float mx[2][2] = {{-INFINITY, -INFINITY}, {-INFINITY, -INFINITY}};
    float lx[2][2] = {{0.f, 0.f}, {0.f, 0.f}};

    for (int s0 = 0; s0 < T_LEN; s0 += 32) {
        __syncthreads();
#pragma unroll
        for (int i = 0; i < 4; i++) {
            int idx = tid + i * 128;
            int r = idx >> 4, c = (idx & 15) << 2;
            float4 kv = *(const float4*)(Kp + (size_t)(s0 + r) * KV_DIM + c);
            uint32_t* pk = &Ks[r * SMS + c];
            pk[0] = f2tf32(kv.x); pk[1] = f2tf32(kv.y);
            pk[2] = f2tf32(kv.z); pk[3] = f2tf32(kv.w);
            float4 vv = *(const float4*)(Vp + (size_t)(s0 + r) * KV_DIM + c);
            uint32_t* pv = &Vs[r * SMS + c];
            pv[0] = f2tf32(vv.x); pv[1] = f2tf32(vv.y);
            pv[2] = f2tf32(vv.z); pv[3] = f2tf32(vv.w);
        }
        __syncthreads();

        float sA[2][4][4];
#pragma unroll
        for (int m = 0; m < 2; m++)
#pragma unroll
            for (int nt = 0; nt < 4; nt++)
#pragma unroll
                for (int i = 0; i < 4; i++) sA[m][nt][i] = 0.f;
#pragma unroll
        for (int kt = 0; kt < 8; kt++) {
#pragma unroll
            for (int nt = 0; nt < 4; nt++) {
                uint32_t bfr[2];
                bfr[0] = Ks[(nt * 8 + g) * SMS + kt * 8 + q];
                bfr[1] = Ks[(nt * 8 + g) * SMS + kt * 8 + q + 4];
                mma_m16n8k8(sA[0][nt], qf[0][kt], bfr);
                mma_m16n8k8(sA[1][nt], qf[1][kt], bfr);
            }
        }

#pragma unroll
        for (int m = 0; m < 2; m++) {
            float t0 = -INFINITY, t1 = -INFINITY;
#pragma unroll
            for (int nt = 0; nt < 4; nt++) {
                t0 = fmaxf(t0, fmaxf(sA[m][nt][0], sA[m][nt][1]));
                t1 = fmaxf(t1, fmaxf(sA[m][nt][2], sA[m][nt][3]));
            }
            t0 = fmaxf(t0, __shfl_xor_sync(0xffffffffu, t0, 1));
            t0 = fmaxf(t0, __shfl_xor_sync(0xffffffffu, t0, 2));
            t1 = fmaxf(t1, __shfl_xor_sync(0xffffffffu, t1, 1));
            t1 = fmaxf(t1, __shfl_xor_sync(0xffffffffu, t1, 2));
            float nm0 = fmaxf(mx[m][0], t0), nm1 = fmaxf(mx[m][1], t1);
            float c0 = fex2(mx[m][0] - nm0), c1 = fex2(mx[m][1] - nm1);

            uint32_t* P0 = &Ps[(warp * 32 + m * 16 + g) * PSS];
            uint32_t* P1 = &Ps[(warp * 32 + m * 16 + g + 8) * PSS];
            float ps0 = 0.f, ps1 = 0.f;
#pragma unroll
            for (int nt = 0; nt < 4; nt++) {
                float p00 = fex2(sA[m][nt][0] - nm0);
                float p01 = fex2(sA[m][nt][1] - nm0);
                float p10 = fex2(sA[m][nt][2] - nm1);
                float p11 = fex2(sA[m][nt][3] - nm1);
                ps0 += p00 + p01;
                ps1 += p10 + p11;
                P0[nt * 8 + 2 * q]     = f2tf32(p00);
                P0[nt * 8 + 2 * q + 1] = f2tf32(p01);
                P1[nt * 8 + 2 * q]     = f2tf32(p10);
                P1[nt * 8 + 2 * q + 1] = f2tf32(p11);
            }
            ps0 += __shfl_xor_sync(0xffffffffu, ps0, 1);
            ps0 += __shfl_xor_sync(0xffffffffu, ps0, 2);
            ps1 += __shfl_xor_sync(0xffffffffu, ps1, 1);
            ps1 += __shfl_xor_sync(0xffffffffu, ps1, 2);
            lx[m][0] = lx[m][0] * c0 + ps0;
            lx[m][1] = lx[m][1] * c1 + ps1;
            mx[m][0] = nm0; mx[m][1] = nm1;
#pragma unroll
            for (int nt = 0; nt < 8; nt++) {
                o[m][nt][0] *= c0; o[m][nt][1] *= c0;
                o[m][nt][2] *= c1; o[m][nt][3] *= c1;
            }
        }
        __syncwarp();

#pragma unroll
        for (int kt = 0; kt < 4; kt++) {
            uint32_t a0[4], a1[4];
            a0[0] = Ps[(warp * 32 + g) * PSS + kt * 8 + q];
            a0[1] = Ps[(warp * 32 + g + 8) * PSS + kt * 8 + q];
            a0[2] = Ps[(warp * 32 + g) * PSS + kt * 8 + q + 4];
            a0[3] = Ps[(warp * 32 + g + 8) * PSS + kt * 8 + q + 4];
            a1[0] = Ps[(warp * 32 + 16 + g) * PSS + kt * 8 + q];
            a1[1] = Ps[(warp * 32 + 16 + g + 8) * PSS + kt * 8 + q];
            a1[2] = Ps[(warp * 32 + 16 + g) * PSS + kt * 8 + q + 4];
            a1[3] = Ps[(warp * 32 + 16 + g + 8) * PSS + kt * 8 + q + 4];
#pragma unroll
            for (int nt = 0; nt < 8; nt++) {
                uint32_t bfr[2];
                bfr[0] = Vs[(kt * 8 + q) * SMS + nt * 8 + g];
                bfr[1] = Vs[(kt * 8 + q + 4) * SMS + nt * 8 + g];
                mma_m16n8k8(o[0][nt], a0, bfr);
                mma_m16n8k8(o[1][nt], a1, bfr);
            }
        }
    }

#pragma unroll
    for (int m = 0; m < 2; m++) {
        float inv0 = 1.f / lx[m][0], inv1 = 1.f / lx[m][1];
        const size_t yb =
            (size_t)(b * T_LEN + qrow0 + m * 16 + g) * D_MODEL + h * D_HEAD;
#pragma unroll
        for (int nt = 0; nt < 8; nt++) {
            int col = nt * 8 + 2 * q;
            *(float2*)(Yg + yb + col) =
                make_float2(o[m][nt][0] * inv0, o[m][nt][1] * inv0);
            *(float2*)(Yg + yb + (size_t)8 * D_MODEL + col) =
                make_float2(o[m][nt][2] * inv1, o[m][nt][3] * inv1);
        }
    }
}

// ---------------------------------------------------------------------------
extern "C" void kernel_launch(void* const* d_in, const int* in_sizes, int n_in,
                              void* d_out, int out_size) {
    (void)in_sizes; (void)n_in; (void)out_size;
    const float* x   = (const float*)d_in[0];
    const float* Wq  = (const float*)d_in[1];
    const float* Wk  = (const float*)d_in[2];
    const float* Wv  = (const float*)d_in[3];
    const float* Wpj = (const float*)d_in[4];
    float* out = (float*)d_out;

    float *pQ, *pK, *pV, *pY;
    cudaGetSymbolAddress((void**)&pQ, g_Q);
    cudaGetSymbolAddress((void**)&pK, g_K);
    cudaGetSymbolAddress((void**)&pV, g_V);
    cudaGetSymbolAddress((void**)&pY, g_Y);

    // Fused QKV projection (N = 1024 | 512 | 512 concatenated on grid.x)
    gemm_qkv<<<dim3(2048 / 64, ROWS / 128), 128>>>(x, Wq, Wk, Wv, pQ, pK, pV);
    attn_tf32<<<dim3(T_LEN / 128, N_HEADS, BATCH), 128>>>(pQ, pK, pV, pY);
    gemm_proj<<<dim3(D_MODEL / 64, ROWS / 128), 128>>>(pY, Wpj, out);
}

// round 17
// speedup vs baseline: 1.7462x; 1.1590x over previous
#include <cuda_runtime.h>
#include <cuda_bf16.h>
#include <cstdint>
#include <math.h>

// ---------------------------------------------------------------------------
// GQA block. R15:
//  - GEMMs: pre-split (hi|lo) bf16-pair planes + cp.async double buffer,
//    3 x m16n8k16 per K=16 (split-bf16, ~16-bit effective).   [kept from R14]
//  - Attention: tf32 PV path REVERTED to the proven R12 scheme (bf16 P/V
//    failed: weighted-mean output keeps quantization error at full relative
//    scale -> need tf32's 11-bit mantissa). Epilogue writes Y split planes.
// ---------------------------------------------------------------------------

#define D_MODEL   1024
#define T_LEN     2048
#define BATCH     2
#define N_HEADS   16
#define D_HEAD    64
#define KV_DIM    512
#define ROWS      (BATCH * T_LEN)  // 4096
#define KP        (D_MODEL / 2)    // 512 uint2 per row
#define QSC 0.18033688011112042f   // scale * log2(e)

__device__ float g_Q[ROWS * D_MODEL];
__device__ float g_K[ROWS * KV_DIM];
__device__ float g_V[ROWS * KV_DIM];
__device__ __align__(16) uint2 g_xs[ROWS * KP];
__device__ __align__(16) uint2 g_ys[ROWS * KP];
__device__ __align__(16) uint2 g_wqs[D_MODEL * KP];
__device__ __align__(16) uint2 g_wks[KV_DIM * KP];
__device__ __align__(16) uint2 g_wvs[KV_DIM * KP];
__device__ __align__(16) uint2 g_wps[D_MODEL * KP];

__device__ __forceinline__ uint32_t f2tf32(float x) {
    uint32_t y;
    asm("cvt.rna.tf32.f32 %0, %1;" : "=r"(y) : "f"(x));
    return y;
}
__device__ __forceinline__ float fex2(float x) {
    float y;
    asm("ex2.approx.f32 %0, %1;" : "=f"(y) : "f"(x));
    return y;
}
__device__ __forceinline__ uint2 split2_bf16(float x, float y) {
    __nv_bfloat16 hx = __float2bfloat16_rn(x);
    __nv_bfloat16 hy = __float2bfloat16_rn(y);
    __nv_bfloat16 lx = __float2bfloat16_rn(x - __bfloat162float(hx));
    __nv_bfloat16 ly = __float2bfloat16_rn(y - __bfloat162float(hy));
    uint2 r;
    r.x = ((uint32_t)__bfloat16_as_ushort(hy) << 16) | __bfloat16_as_ushort(hx);
    r.y = ((uint32_t)__bfloat16_as_ushort(ly) << 16) | __bfloat16_as_ushort(lx);
    return r;
}
__device__ __forceinline__ void mma_bf16_k16(float c[4], const uint32_t a[4],
                                             const uint32_t b[2]) {
    asm volatile(
        "mma.sync.aligned.m16n8k16.row.col.f32.bf16.bf16.f32 "
        "{%0,%1,%2,%3}, {%4,%5,%6,%7}, {%8,%9}, {%0,%1,%2,%3};"
        : "+f"(c[0]), "+f"(c[1]), "+f"(c[2]), "+f"(c[3])
        : "r"(a[0]), "r"(a[1]), "r"(a[2]), "r"(a[3]), "r"(b[0]), "r"(b[1]));
}
__device__ __forceinline__ void mma_m16n8k8(float c[4], const uint32_t a[4],
                                            const uint32_t b[2]) {
    asm volatile(
        "mma.sync.aligned.m16n8k8.row.col.f32.tf32.tf32.f32 "
        "{%0,%1,%2,%3}, {%4,%5,%6,%7}, {%8,%9}, {%0,%1,%2,%3};"
        : "+f"(c[0]), "+f"(c[1]), "+f"(c[2]), "+f"(c[3])
        : "r"(a[0]), "r"(a[1]), "r"(a[2]), "r"(a[3]), "r"(b[0]), "r"(b[1]));
}
__device__ __forceinline__ uint32_t smem_u32(const void* p) {
    return (uint32_t)__cvta_generic_to_shared(p);
}
__device__ __forceinline__ void cp16(uint32_t dst, const void* src) {
    asm volatile("cp.async.cg.shared.global [%0], [%1], 16;\n"
                 :: "r"(dst), "l"(src));
}
__device__ __forceinline__ void cp_commit() {
    asm volatile("cp.async.commit_group;\n");
}
template <int N> __device__ __forceinline__ void cp_wait() {
    asm volatile("cp.async.wait_group %0;\n" :: "n"(N));
}

// ---------------------------------------------------------------------------
__global__ void split_planes(const float4* __restrict__ src,
                             uint4* __restrict__ dst, int n4) {
    int i = blockIdx.x * blockDim.x + threadIdx.x;
    if (i < n4) {
        float4 v = src[i];
        uint2 d0 = split2_bf16(v.x, v.y);
        uint2 d1 = split2_bf16(v.z, v.w);
        dst[i] = make_uint4(d0.x, d0.y, d1.x, d1.y);
    }
}

// ---------------------------------------------------------------------------
// Split-bf16 GEMM with cp.async double buffering (proven layout, R11 frags).
// Block 128x64, 4 warps (32x64 warp tile), k-step 32 (16 uint2/row), smem
// row stride 20 uint2 -> conflict-free 64-bit fragment phases.
// ---------------------------------------------------------------------------
#define GS_A (128 * 20)
#define GS_W (64 * 20)
#define GEMM_SMEM ((GS_A + GS_W) * 2 * (int)sizeof(uint2))  // 61440 B

__device__ __forceinline__ void gemm_body(
    const uint2* __restrict__ A, const uint2* __restrict__ W,
    float* __restrict__ C, int m0, int n0, int N, uint2* smem) {
    uint2* sA = smem;
    uint2* sW = smem + 2 * GS_A;

    const int tid  = threadIdx.x;
    const int warp = tid >> 5;
    const int lane = tid & 31;
    const int g    = lane >> 2;
    const int q    = lane & 3;

    auto issue = [&](int s) {
        uint2* bufA = sA + (s & 1) * GS_A;
        uint2* bufW = sW + (s & 1) * GS_W;
        const int kb = s * 16;
#pragma unroll
        for (int i = 0; i < 8; i++) {
            int id = tid + i * 128, r = id >> 3, c = (id & 7) * 2;
            cp16(smem_u32(bufA + r * 20 + c),
                 A + (size_t)(m0 + r) * KP + kb + c);
        }
#pragma unroll
        for (int i = 0; i < 4; i++) {
            int id = tid + i * 128, r = id >> 3, c = (id & 7) * 2;
            cp16(smem_u32(bufW + r * 20 + c),
                 W + (size_t)(n0 + r) * KP + kb + c);
        }
        cp_commit();
    };

    float acc[2][8][4];
#pragma unroll
    for (int m = 0; m < 2; m++)
#pragma unroll
        for (int nt = 0; nt < 8; nt++)
#pragma unroll
            for (int i = 0; i < 4; i++) acc[m][nt][i] = 0.f;

    issue(0);
    for (int s = 0; s < 32; s++) {
        if (s < 31) { issue(s + 1); cp_wait<1>(); }
        else        { cp_wait<0>(); }
        __syncthreads();
        const uint2* bA = sA + (s & 1) * GS_A;
        const uint2* bW = sW + (s & 1) * GS_W;
        const int mr = warp * 32;
#pragma unroll
        for (int kk = 0; kk < 2; kk++) {
            uint32_t ah[2][4], al[2][4];
#pragma unroll
            for (int m = 0; m < 2; m++) {
                uint2 a0 = bA[(mr + m * 16 + g) * 20 + kk * 8 + q];
                uint2 a1 = bA[(mr + m * 16 + g + 8) * 20 + kk * 8 + q];
                uint2 a2 = bA[(mr + m * 16 + g) * 20 + kk * 8 + q + 4];
                uint2 a3 = bA[(mr + m * 16 + g + 8) * 20 + kk * 8 + q + 4];
                ah[m][0] = a0.x; ah[m][1] = a1.x; ah[m][2] = a2.x; ah[m][3] = a3.x;
                al[m][0] = a0.y; al[m][1] = a1.y; al[m][2] = a2.y; al[m][3] = a3.y;
            }
#pragma unroll
            for (int nt = 0; nt < 8; nt++) {
                uint2 b0 = bW[(nt * 8 + g) * 20 + kk * 8 + q];
                uint2 b1 = bW[(nt * 8 + g) * 20 + kk * 8 + q + 4];
                uint32_t bh[2] = {b0.x, b1.x};
                uint32_t bl[2] = {b0.y, b1.y};
#pragma unroll
                for (int m = 0; m < 2; m++) {
                    mma_bf16_k16(acc[m][nt], ah[m], bh);
                    mma_bf16_k16(acc[m][nt], ah[m], bl);
                    mma_bf16_k16(acc[m][nt], al[m], bh);
                }
            }
        }
        __syncthreads();
    }

#pragma unroll
    for (int m = 0; m < 2; m++) {
        const int row = m0 + warp * 32 + m * 16 + g;
#pragma unroll
        for (int nt = 0; nt < 8; nt++) {
            int col = n0 + nt * 8 + q * 2;
            *(float2*)(C + (size_t)row * N + col) =
                make_float2(acc[m][nt][0], acc[m][nt][1]);
            *(float2*)(C + (size_t)(row + 8) * N + col) =
                make_float2(acc[m][nt][2], acc[m][nt][3]);
        }
    }
}

__global__ __launch_bounds__(128) void gemm_qkv(
    const uint2* __restrict__ xs,
    const uint2* __restrict__ wqs, const uint2* __restrict__ wks,
    const uint2* __restrict__ wvs,
    float* __restrict__ Q, float* __restrict__ K, float* __restrict__ V) {
    extern __shared__ uint2 smem[];
    const int n0g = blockIdx.x * 64;
    const int m0  = blockIdx.y * 128;
    const uint2* W; float* C; int n0, N;
    if (n0g < 1024)      { W = wqs; C = Q; n0 = n0g;        N = 1024; }
    else if (n0g < 1536) { W = wks; C = K; n0 = n0g - 1024; N = 512;  }
    else                 { W = wvs; C = V; n0 = n0g - 1536; N = 512;  }
    gemm_body(xs, W, C, m0, n0, N, smem);
}

__global__ __launch_bounds__(128) void gemm_proj(
    const uint2* __restrict__ ys, const uint2* __restrict__ wps,
    float* __restrict__ C) {
    extern __shared__ uint2 smem[];
    gemm_body(ys, wps, C, blockIdx.y * 128, blockIdx.x * 64, D_MODEL, smem);
}

// ---------------------------------------------------------------------------
// Flash attention — proven R12 tf32 scheme (305us, rel_err 2.9e-4).
// S = QK^T tf32 k8; softmax log2-domain; P via smem as tf32; PV tf32 k8.
// Only change: epilogue writes Y directly as (hi|lo) split planes.
// ---------------------------------------------------------------------------
#define SMS 68
#define PSS 36

__global__ __launch_bounds__(128) void attn_kernel(
    const float* __restrict__ Qg, const float* __restrict__ Kg,
    const float* __restrict__ Vg, uint2* __restrict__ Ys) {
    __shared__ uint32_t Ks[32 * SMS];
    __shared__ uint32_t Vs[32 * SMS];
    __shared__ uint32_t Ps[128 * PSS];

    const int tid  = threadIdx.x;
    const int warp = tid >> 5;
    const int lane = tid & 31;
    const int g    = lane >> 2;
    const int q    = lane & 3;
    const int b    = blockIdx.z;
    const int h    = blockIdx.y;
    const int qrow0 = blockIdx.x * 128 + warp * 32;

    const float* Qp = Qg + (size_t)b * T_LEN * D_MODEL + h * D_HEAD;
    const float* Kp = Kg + (size_t)b * T_LEN * KV_DIM + (h >> 1) * D_HEAD;
    const float* Vp = Vg + (size_t)b * T_LEN * KV_DIM + (h >> 1) * D_HEAD;

    uint32_t qf[2][8][4];
#pragma unroll
    for (int m = 0; m < 2; m++) {
        const float* Q0 = Qp + (size_t)(qrow0 + m * 16 + g) * D_MODEL;
        const float* Q1 = Qp + (size_t)(qrow0 + m * 16 + g + 8) * D_MODEL;
#pragma unroll
        for (int kt = 0; kt < 8; kt++) {
            qf[m][kt][0] = f2tf32(Q0[kt * 8 + q] * QSC);
            qf[m][kt][1] = f2tf32(Q1[kt * 8 + q] * QSC);
            qf[m][kt][2] = f2tf32(Q0[kt * 8 + q + 4] * QSC);
            qf[m][kt][3] = f2tf32(Q1[kt * 8 + q + 4] * QSC);
        }
    }

    float o[2][8][4];
#pragma unroll
    for (int m = 0; m < 2; m++)
#pragma unroll
        for (int nt = 0; nt < 8; nt++)
#pragma unroll
            for (int i = 0; i < 4; i++) o[m][nt][i] = 0.f;
    float mx[2][2] = {{-INFINITY, -INFINITY}, {-INFINITY, -INFINITY}};
    float lx[2][2] = {{0.f, 0.f}, {0.f, 0.f}};

    for (int s0 = 0; s0 < T_LEN; s0 += 32) {
        __syncthreads();
#pragma unroll
        for (int i = 0; i < 4; i++) {
            int idx = tid + i * 128;
            int r = idx >> 4, c = (idx & 15) << 2;
            float4 kv = *(const float4*)(Kp + (size_t)(s0 + r) * KV_DIM + c);
            uint32_t* pk = &Ks[r * SMS + c];
            pk[0] = f2tf32(kv.x); pk[1] = f2tf32(kv.y);
            pk[2] = f2tf32(kv.z); pk[3] = f2tf32(kv.w);
            float4 vv = *(const float4*)(Vp + (size_t)(s0 + r) * KV_DIM + c);
            uint32_t* pv = &Vs[r * SMS + c];
            pv[0] = f2tf32(vv.x); pv[1] = f2tf32(vv.y);
            pv[2] = f2tf32(vv.z); pv[3] = f2tf32(vv.w);
        }
        __syncthreads();

        float sA[2][4][4];
#pragma unroll
        for (int m = 0; m < 2; m++)
#pragma unroll
            for (int nt = 0; nt < 4; nt++)
#pragma unroll
                for (int i = 0; i < 4; i++) sA[m][nt][i] = 0.f;
#pragma unroll
        for (int kt = 0; kt < 8; kt++) {
#pragma unroll
            for (int nt = 0; nt < 4; nt++) {
                uint32_t bfr[2];
                bfr[0] = Ks[(nt * 8 + g) * SMS + kt * 8 + q];
                bfr[1] = Ks[(nt * 8 + g) * SMS + kt * 8 + q + 4];
                mma_m16n8k8(sA[0][nt], qf[0][kt], bfr);
                mma_m16n8k8(sA[1][nt], qf[1][kt], bfr);
            }
        }

#pragma unroll
        for (int m = 0; m < 2; m++) {
            float t0 = -INFINITY, t1 = -INFINITY;
#pragma unroll
            for (int nt = 0; nt < 4; nt++) {
                t0 = fmaxf(t0, fmaxf(sA[m][nt][0], sA[m][nt][1]));
                t1 = fmaxf(t1, fmaxf(sA[m][nt][2], sA[m][nt][3]));
            }
            t0 = fmaxf(t0, __shfl_xor_sync(0xffffffffu, t0, 1));
            t0 = fmaxf(t0, __shfl_xor_sync(0xffffffffu, t0, 2));
            t1 = fmaxf(t1, __shfl_xor_sync(0xffffffffu, t1, 1));
            t1 = fmaxf(t1, __shfl_xor_sync(0xffffffffu, t1, 2));
            float nm0 = fmaxf(mx[m][0], t0), nm1 = fmaxf(mx[m][1], t1);
            float c0 = fex2(mx[m][0] - nm0), c1 = fex2(mx[m][1] - nm1);

            uint32_t* P0 = &Ps[(warp * 32 + m * 16 + g) * PSS];
            uint32_t* P1 = &Ps[(warp * 32 + m * 16 + g + 8) * PSS];
            float ps0 = 0.f, ps1 = 0.f;
#pragma unroll
            for (int nt = 0; nt < 4; nt++) {
                float p00 = fex2(sA[m][nt][0] - nm0);
                float p01 = fex2(sA[m][nt][1] - nm0);
                float p10 = fex2(sA[m][nt][2] - nm1);
                float p11 = fex2(sA[m][nt][3] - nm1);
                ps0 += p00 + p01;
                ps1 += p10 + p11;
                P0[nt * 8 + 2 * q]     = f2tf32(p00);
                P0[nt * 8 + 2 * q + 1] = f2tf32(p01);
                P1[nt * 8 + 2 * q]     = f2tf32(p10);
                P1[nt * 8 + 2 * q + 1] = f2tf32(p11);
            }
            ps0 += __shfl_xor_sync(0xffffffffu, ps0, 1);
            ps0 += __shfl_xor_sync(0xffffffffu, ps0, 2);
            ps1 += __shfl_xor_sync(0xffffffffu, ps1, 1);
            ps1 += __shfl_xor_sync(0xffffffffu, ps1, 2);
            lx[m][0] = lx[m][0] * c0 + ps0;
            lx[m][1] = lx[m][1] * c1 + ps1;
            mx[m][0] = nm0; mx[m][1] = nm1;
#pragma unroll
            for (int nt = 0; nt < 8; nt++) {
                o[m][nt][0] *= c0; o[m][nt][1] *= c0;
                o[m][nt][2] *= c1; o[m][nt][3] *= c1;
            }
        }
        __syncwarp();

#pragma unroll
        for (int kt = 0; kt < 4; kt++) {
            uint32_t a0[4], a1[4];
            a0[0] = Ps[(warp * 32 + g) * PSS + kt * 8 + q];
            a0[1] = Ps[(warp * 32 + g + 8) * PSS + kt * 8 + q];
            a0[2] = Ps[(warp * 32 + g) * PSS + kt * 8 + q + 4];
            a0[3] = Ps[(warp * 32 + g + 8) * PSS + kt * 8 + q + 4];
            a1[0] = Ps[(warp * 32 + 16 + g) * PSS + kt * 8 + q];
            a1[1] = Ps[(warp * 32 + 16 + g + 8) * PSS + kt * 8 + q];
            a1[2] = Ps[(warp * 32 + 16 + g) * PSS + kt * 8 + q + 4];
            a1[3] = Ps[(warp * 32 + 16 + g + 8) * PSS + kt * 8 + q + 4];
#pragma unroll
            for (int nt = 0; nt < 8; nt++) {
                uint32_t bfr[2];
                bfr[0] = Vs[(kt * 8 + q) * SMS + nt * 8 + g];
                bfr[1] = Vs[(kt * 8 + q + 4) * SMS + nt * 8 + g];
                mma_m16n8k8(o[0][nt], a0, bfr);
                mma_m16n8k8(o[1][nt], a1, bfr);
            }
        }
    }

    // normalize + write Y directly as split planes (fp32 -> hi/lo, ~1e-5)
#pragma unroll
    for (int m = 0; m < 2; m++) {
        float inv0 = 1.f / lx[m][0], inv1 = 1.f / lx[m][1];
        const size_t r0 = (size_t)(b * T_LEN + qrow0 + m * 16 + g);
#pragma unroll
        for (int nt = 0; nt < 8; nt++) {
            int cp = h * 32 + nt * 4 + q;  // column-pair index
            Ys[r0 * KP + cp] =
                split2_bf16(o[m][nt][0] * inv0, o[m][nt][1] * inv0);
            Ys[(r0 + 8) * KP + cp] =
                split2_bf16(o[m][nt][2] * inv1, o[m][nt][3] * inv1);
        }
    }
}

// ---------------------------------------------------------------------------
extern "C" void kernel_launch(void* const* d_in, const int* in_sizes, int n_in,
                              void* d_out, int out_size) {
    (void)in_sizes; (void)n_in; (void)out_size;
    const float* x   = (const float*)d_in[0];
    const float* Wq  = (const float*)d_in[1];
    const float* Wk  = (const float*)d_in[2];
    const float* Wv  = (const float*)d_in[3];
    const float* Wpj = (const float*)d_in[4];
    float* out = (float*)d_out;

    float *pQ, *pK, *pV;
    uint2 *pxs, *pys, *pwqs, *pwks, *pwvs, *pwps;
    cudaGetSymbolAddress((void**)&pQ, g_Q);
    cudaGetSymbolAddress((void**)&pK, g_K);
    cudaGetSymbolAddress((void**)&pV, g_V);
    cudaGetSymbolAddress((void**)&pxs, g_xs);
    cudaGetSymbolAddress((void**)&pys, g_ys);
    cudaGetSymbolAddress((void**)&pwqs, g_wqs);
    cudaGetSymbolAddress((void**)&pwks, g_wks);
    cudaGetSymbolAddress((void**)&pwvs, g_wvs);
    cudaGetSymbolAddress((void**)&pwps, g_wps);

    cudaFuncSetAttribute(gemm_qkv,
                         cudaFuncAttributeMaxDynamicSharedMemorySize, GEMM_SMEM);
    cudaFuncSetAttribute(gemm_proj,
                         cudaFuncAttributeMaxDynamicSharedMemorySize, GEMM_SMEM);

    split_planes<<<(ROWS * D_MODEL / 4 + 255) / 256, 256>>>(
        (const float4*)x, (uint4*)pxs, ROWS * D_MODEL / 4);
    split_planes<<<(D_MODEL * D_MODEL / 4 + 255) / 256, 256>>>(
        (const float4*)Wq, (uint4*)pwqs, D_MODEL * D_MODEL / 4);
    split_planes<<<(KV_DIM * D_MODEL / 4 + 255) / 256, 256>>>(
        (const float4*)Wk, (uint4*)pwks, KV_DIM * D_MODEL / 4);
    split_planes<<<(KV_DIM * D_MODEL / 4 + 255) / 256, 256>>>(
        (const float4*)Wv, (uint4*)pwvs, KV_DIM * D_MODEL / 4);
    split_planes<<<(D_MODEL * D_MODEL / 4 + 255) / 256, 256>>>(
        (const float4*)Wpj, (uint4*)pwps, D_MODEL * D_MODEL / 4);

    gemm_qkv<<<dim3(2048 / 64, ROWS / 128), 128, GEMM_SMEM>>>(
        pxs, pwqs, pwks, pwvs, pQ, pK, pV);
    attn_kernel<<<dim3(T_LEN / 128, N_HEADS, BATCH), 128>>>(pQ, pK, pV, pys);
    gemm_proj<<<dim3(D_MODEL / 64, ROWS / 128), 128, GEMM_SMEM>>>(
        pys, pwps, out);
}